// round 6
// baseline (speedup 1.0000x reference)
#include <cuda_runtime.h>

// Problem constants (fixed shapes per reference setup_inputs)
#define SS 512
#define DD 2640
#define MM 64
// Only batch 7 contributes. Final scale = 1/(S*(S-1)) / M / (B*100)
// mask_list is int32 on device (JAX x64 disabled downcasts jnp.int64).
//
// Norm expansion: sq_dist(m,s) = ||r_m||^2 + ||i_s||^2 - 2*(r_m . i_s).
// kA computes dot-product partials (the only O(M*S*D) term) + norm partials.

// Kernel A tiling: grid (4 s-tiles, 66 d-splits) = 264 CTAs, 256 threads.
// Tile: 64 m x 128 s x 40 d per CTA, single staged chunk. 2 CTAs/SM.
#define ND    66      // d splits
#define DPC   40      // d per CTA
#define CHQ   10      // float4 (d-quads) per row
#define ROWS  192     // 64 target rows + 128 input rows
#define R4    193     // padded row stride in float4 units (odd -> conflict-light)
#define STILE 128     // s per CTA
#define NELEM (ROWS * CHQ)   // 1920 staging float4s

__device__ float g_part[ND * MM * SS];   // dot partials: 66*64*512*4B = 8.65 MB
__device__ float g_ni[ND * SS];          // input-row norm partials
__device__ float g_nr[ND * MM];          // target-row norm partials
__device__ float g_mred[MM];
__device__ int   g_ticket = 0;

// ---------------------------------------------------------------------------
// Kernel A: dot-product partials, f32x2-packed. smem trp[q][row] = float4 of
// 4 consecutive d. Rows 0..63 = gathered target rows, 64..191 = -input rows
// (negated so acc accumulates -r.i; kB applies sq = nr + ni + 2*acc).
// Thread (lane 0..31, wid 0..7) owns m = 8*wid..8*wid+7, s = lane+{0,32,64,96}.
// ---------------------------------------------------------------------------
__global__ __launch_bounds__(256, 2) void kA(const float* __restrict__ input,
                                             const int* __restrict__ mask,
                                             const float* __restrict__ target)
{
    __shared__ __align__(16) float4 trp[CHQ * R4];   // 10*193*16 = 30880 B
    __shared__ const float* rowptr[ROWS];

    const int tid  = threadIdx.x;
    const int lane = tid & 31;
    const int wid  = tid >> 5;
    const int sbase = blockIdx.x * STILE;
    const int dbase = blockIdx.y * DPC;

    if (tid < MM) {
        int im = mask[7 * MM + tid];
        rowptr[tid] = target + ((size_t)7 * SS + (size_t)im) * DD + dbase;
    } else if (tid < ROWS) {
        rowptr[tid] = input + ((size_t)7 * SS + (size_t)(sbase + tid - MM)) * DD + dbase;
    }
    __syncthreads();

    // ---- stage global -> transposed smem (8 independent LDG.128 in flight) ----
    #pragma unroll
    for (int k = 0; k < 8; ++k) {
        int i = tid + k * 256;
        if (i < NELEM) {
            int row = i / CHQ, c = i - row * CHQ;
            float4 v = *(reinterpret_cast<const float4*>(rowptr[row]) + c);
            if (row >= MM) { v.x = -v.x; v.y = -v.y; v.z = -v.z; v.w = -v.w; }
            trp[c * R4 + row] = v;
        }
    }
    __syncthreads();

    // ---- norm partials from staged tile (negation is square-invariant) ----
    if (tid < ROWS) {
        float ns = 0.0f;
        #pragma unroll
        for (int c = 0; c < CHQ; ++c) {
            float4 v = trp[c * R4 + tid];
            ns += v.x * v.x + v.y * v.y + v.z * v.z + v.w * v.w;
        }
        if (tid < MM) {
            if (blockIdx.x == 0) g_nr[blockIdx.y * MM + tid] = ns;
        } else {
            g_ni[blockIdx.y * SS + sbase + (tid - MM)] = ns;
        }
    }

    // ---- compute: 10 d-quad iterations, 64 packed FMAs + 12 LDS each ----
    unsigned long long acc[32];
    #pragma unroll
    for (int i = 0; i < 32; ++i) acc[i] = 0ull;   // float2(0,0)

    #pragma unroll 2
    for (int q = 0; q < CHQ; ++q) {
        const float4* base = trp + q * R4;
        ulonglong2 iv[4];
        #pragma unroll
        for (int b = 0; b < 4; ++b)   // s rows: lane-contiguous LDS.128
            iv[b] = *reinterpret_cast<const ulonglong2*>(base + MM + lane + 32 * b);
        #pragma unroll
        for (int a = 0; a < 8; ++a) { // m rows: warp-broadcast LDS.128
            ulonglong2 rv = *reinterpret_cast<const ulonglong2*>(base + 8 * wid + a);
            #pragma unroll
            for (int b = 0; b < 4; ++b) {
                asm("fma.rn.f32x2 %0, %1, %2, %0;"
                    : "+l"(acc[a * 4 + b]) : "l"(rv.x), "l"(iv[b].x));
                asm("fma.rn.f32x2 %0, %1, %2, %0;"
                    : "+l"(acc[a * 4 + b]) : "l"(rv.y), "l"(iv[b].y));
            }
        }
    }

    // ---- epilogue: fold packed halves, write dot partials (coalesced) ----
    // acc holds sum of r*(-i) = -dot.
    float* outp = g_part + (size_t)blockIdx.y * (MM * SS) + sbase;
    #pragma unroll
    for (int a = 0; a < 8; ++a) {
        int m = 8 * wid + a;
        #pragma unroll
        for (int b = 0; b < 4; ++b) {
            unsigned long long v = acc[a * 4 + b];
            float lo = __uint_as_float((unsigned)(v & 0xffffffffu));
            float hi = __uint_as_float((unsigned)(v >> 32));
            outp[(size_t)m * SS + lane + 32 * b] = lo + hi;   // = -dot partial
        }
    }
}

// ---------------------------------------------------------------------------
// Kernel B: recombine norms + dot, hinge, reduce. Grid: 64 CTAs (one per m).
// Last block (atomic ticket) performs the final 64-way sum deterministically.
// ---------------------------------------------------------------------------
__global__ __launch_bounds__(256) void kB(const int* __restrict__ mask,
                                          float* __restrict__ out)
{
    const int m   = blockIdx.x;
    const int tid = threadIdx.x;
    const int im  = mask[7 * MM + m];

    __shared__ float ni_s[SS];
    __shared__ float red[256];

    // input-row norms: ni[s] = sum_z g_ni[z][s]  (coalesced over s)
    for (int s = tid; s < SS; s += 256) {
        float v = 0.0f;
        for (int z = 0; z < ND; ++z) v += g_ni[z * SS + s];
        ni_s[s] = v;
    }
    // target-row norm for this m
    red[tid] = (tid < ND) ? g_nr[tid * MM + m] : 0.0f;
    __syncthreads();
    for (int o = 128; o >= 1; o >>= 1) {
        if (tid < o) red[tid] += red[tid + o];
        __syncthreads();
    }
    const float nr = red[0];
    __syncthreads();

    float lsum = 0.0f;
    for (int s = tid; s < SS; s += 256) {
        float ndot = 0.0f;   // accumulates -dot
        for (int z = 0; z < ND; ++z)
            ndot += g_part[(size_t)z * (MM * SS) + (size_t)m * SS + s];
        float sq = nr + ni_s[s] + 2.0f * ndot;
        int d = im - s;
        if (d < 0) d = -d;
        lsum += (d <= 1) ? sq : fmaxf(0.0f, 15000.0f - sq);
    }

    red[tid] = lsum;
    __syncthreads();
    for (int o = 128; o >= 1; o >>= 1) {
        if (tid < o) red[tid] += red[tid + o];
        __syncthreads();
    }
    if (tid == 0) g_mred[m] = red[0];

    // ---- last-block final reduce (deterministic fixed-order sum) ----
    __shared__ int is_last;
    __threadfence();
    if (tid == 0) is_last = (atomicAdd(&g_ticket, 1) == MM - 1);
    __syncthreads();
    if (is_last && tid == 0) {
        __threadfence();
        float tot = 0.0f;
        #pragma unroll
        for (int i = 0; i < MM; ++i) tot += g_mred[i];
        const float scale = (float)(1.0 / (261632.0 * 64.0 * 800.0)); // 1/(S(S-1))/M/(B*100)
        out[0] = tot * scale;
        g_ticket = 0;   // reset for next graph replay
    }
}

// ---------------------------------------------------------------------------
extern "C" void kernel_launch(void* const* d_in, const int* in_sizes, int n_in,
                              void* d_out, int out_size)
{
    const float* input  = (const float*)d_in[0];
    const int*   mask   = (const int*)d_in[1];
    const float* target = (const float*)d_in[2];
    float*       out    = (float*)d_out;

    kA<<<dim3(4, ND), 256>>>(input, mask, target);
    kB<<<MM, 256>>>(mask, out);
}